// round 7
// baseline (speedup 1.0000x reference)
#include <cuda_runtime.h>
#include <math.h>

#define NOBJ  2048
#define EMBED 256
#define NHD   8
#define NP    32
#define HD    32
#define FFN_D 1024
#define HIMG  160
#define WIMG  160
#define HW    (HIMG*WIMG)
#define NUM_IMG 4

// ---- scratch (device globals; no allocations allowed) ----
__device__ float g_loc [NOBJ*NHD*NP*2];   // unnormalized sample coords (ix,iy)
__device__ float g_attn[NOBJ*EMBED];      // attention output (pre w_out)
__device__ float g_x1  [NOBJ*EMBED];      // after w_out + residual (pre LN1)
__device__ float g_x1ln[NOBJ*EMBED];      // after LN1
__device__ float g_hid [NOBJ*FFN_D];      // relu(x@w1+b1)
__device__ float g_x2  [NOBJ*EMBED];      // pre LN2
// transposed feature maps: (img, hw, embed) -- 104.9MB each
__device__ float g_ktr [NUM_IMG*(size_t)HW*EMBED];
__device__ float g_vtr [NUM_IMG*(size_t)HW*EMBED];

// ============================================================================
// Transpose (img, C, HW) -> (img, HW, C) for key & value. 32x32 tiles.
// ============================================================================
__global__ __launch_bounds__(256) void transpose_k(
    const float* __restrict__ key, const float* __restrict__ val)
{
    __shared__ float t[32][33];
    const int img = blockIdx.z >> 1;
    const float* src = (blockIdx.z & 1) ? val : key;
    float* dst = (blockIdx.z & 1) ? g_vtr : g_ktr;
    src += (size_t)img * EMBED * HW;
    dst += (size_t)img * HW * EMBED;
    const int hw0 = blockIdx.x * 32;
    const int c0  = blockIdx.y * 32;
    const int tx = threadIdx.x & 31;
    const int ty = threadIdx.x >> 5;   // 0..7
#pragma unroll
    for (int i = 0; i < 4; i++) {
        int c = c0 + ty + i * 8;
        t[ty + i * 8][tx] = src[(size_t)c * HW + hw0 + tx];
    }
    __syncthreads();
#pragma unroll
    for (int i = 0; i < 4; i++) {
        int hw = hw0 + ty + i * 8;
        dst[(size_t)hw * EMBED + c0 + tx] = t[tx][ty + i * 8];
    }
}

// ============================================================================
// SGEMM: C(MxN) = A(MxK) @ B(KxN)  row-major, 64x64 tile, 128 threads, 4x8 micro
// EPI 0: offsets -> sample coords   EPI 1: +bias +res   EPI 2: relu(+bias)
// EPI 3: +bias +res
// ============================================================================
template<int EPI>
__global__ __launch_bounds__(128) void sgemm_k(
    const float* __restrict__ A, const float* __restrict__ B,
    const float* __restrict__ bias, const float* __restrict__ res,
    float* __restrict__ C, int M, int N, int K,
    const float* __restrict__ xy, const float* __restrict__ strd)
{
    __shared__ float As[16][68];
    __shared__ float Bs[16][68];

    const int tid = threadIdx.x;
    const int tx = tid & 7;
    const int ty = tid >> 3;
    const int row0 = blockIdx.y * 64;
    const int col0 = blockIdx.x * 64;

    float acc[4][8];
#pragma unroll
    for (int i = 0; i < 4; i++)
#pragma unroll
        for (int j = 0; j < 8; j++) acc[i][j] = 0.f;

    for (int kt = 0; kt < K; kt += 16) {
#pragma unroll
        for (int l = 0; l < 2; l++) {
            int idx = tid + l * 128;
            int am = idx >> 2;
            int ak = (idx & 3) << 2;
            float4 av = *(const float4*)(A + (size_t)(row0 + am) * K + kt + ak);
            As[ak + 0][am] = av.x;
            As[ak + 1][am] = av.y;
            As[ak + 2][am] = av.z;
            As[ak + 3][am] = av.w;
            int bk = idx >> 4;
            int bn = (idx & 15) << 2;
            float4 bv = *(const float4*)(B + (size_t)(kt + bk) * N + col0 + bn);
            *(float4*)&Bs[bk][bn] = bv;
        }
        __syncthreads();
#pragma unroll
        for (int k = 0; k < 16; k++) {
            float4 a4 = *(const float4*)&As[k][ty * 4];
            float4 b0 = *(const float4*)&Bs[k][tx * 8];
            float4 b1 = *(const float4*)&Bs[k][tx * 8 + 4];
            float av[4] = {a4.x, a4.y, a4.z, a4.w};
            float bv[8] = {b0.x, b0.y, b0.z, b0.w, b1.x, b1.y, b1.z, b1.w};
#pragma unroll
            for (int i = 0; i < 4; i++)
#pragma unroll
                for (int j = 0; j < 8; j++) acc[i][j] += av[i] * bv[j];
        }
        __syncthreads();
    }

#pragma unroll
    for (int i = 0; i < 4; i++) {
        int row = row0 + ty * 4 + i;
        float st = 0.f, bx = 0.f, by = 0.f;
        if (EPI == 0) { st = strd[row]; bx = xy[2 * row]; by = xy[2 * row + 1]; }
#pragma unroll
        for (int j = 0; j < 8; j++) {
            int col = col0 + tx * 8 + j;
            float v = acc[i][j] + bias[col];
            size_t oidx = (size_t)row * N + col;
            if (EPI == 0) {
                int c = col & 1;
                float base = c ? by : bx;
                float loc = base + v * st;
                float gn  = loc * (2.0f / 640.0f) - 1.0f;
                float iv  = ((gn + 1.0f) * 160.0f - 1.0f) * 0.5f;
                C[oidx] = iv;
            } else if (EPI == 1 || EPI == 3) {
                C[oidx] = v + res[oidx];
            } else {
                C[oidx] = fmaxf(v, 0.f);
            }
        }
    }
}

// ============================================================================
// Sampler v2: 1 block/object, warp = head.
// Phase 1 (lane = point): corner offsets/weights -> smem; mask/x2d samples.
// Phase 2 (lane = channel d): coalesced 128B gathers from transposed k/v,
//   per-point attention dot via warp reduce, v staged in smem.
// ============================================================================
__global__ __launch_bounds__(256) void sampler_k(
    const float* __restrict__ query, const float* __restrict__ x2d,
    const float* __restrict__ maskp, const int*   __restrict__ imgind,
    const float* __restrict__ loc,
    float* __restrict__ outv, float* __restrict__ outa,
    float* __restrict__ outm, float* __restrict__ outx,
    float* __restrict__ attn)
{
    __shared__ float vsm [NHD][HD][NP + 1];  // [h][d][p]
    __shared__ int   soff[NHD][4][NP];       // corner offsets * EMBED
    __shared__ float swt [NHD][4][NP];       // corner weights
    __shared__ float asms[NHD][NP];
    __shared__ float smask[NHD][NP];

    const int n    = blockIdx.x;
    const int tid  = threadIdx.x;
    const int h    = tid >> 5;
    const int lane = tid & 31;
    const int img  = imgind[n];

    // ---------- phase 1: lane = point ----------
    {
        const int p = lane;
        float2 l2 = ((const float2*)loc)[((size_t)n * NHD + h) * NP + p];
        float ix = l2.x, iy = l2.y;
        float x0f = floorf(ix), y0f = floorf(iy);
        float wx1 = ix - x0f,   wy1 = iy - y0f;
        float wx0 = 1.f - wx1,  wy0 = 1.f - wy1;
        int x0 = (int)x0f, y0 = (int)y0f;
        int x1i = x0 + 1,  y1i = y0 + 1;
        int xc0 = min(max(x0, 0), WIMG - 1), xc1 = min(max(x1i, 0), WIMG - 1);
        int yc0 = min(max(y0, 0), HIMG - 1), yc1 = min(max(y1i, 0), HIMG - 1);
        float w00 = wx0 * wy0, w10 = wx1 * wy0, w01 = wx0 * wy1, w11 = wx1 * wy1;
        int o00 = yc0 * WIMG + xc0, o10 = yc0 * WIMG + xc1;
        int o01 = yc1 * WIMG + xc0, o11 = yc1 * WIMG + xc1;

        soff[h][0][p] = o00 * EMBED;  swt[h][0][p] = w00;
        soff[h][1][p] = o10 * EMBED;  swt[h][1][p] = w10;
        soff[h][2][p] = o01 * EMBED;  swt[h][2][p] = w01;
        soff[h][3][p] = o11 * EMBED;  swt[h][3][p] = w11;

        // mask: zeros padding
        bool vx0 = (x0  >= 0) && (x0  < WIMG), vx1 = (x1i >= 0) && (x1i < WIMG);
        bool vy0 = (y0  >= 0) && (y0  < HIMG), vy1 = (y1i >= 0) && (y1i < HIMG);
        const float* mb = maskp + (size_t)img * HW;
        float mval = 0.f;
        if (vx0 && vy0) mval += w00 * mb[o00];
        if (vx1 && vy0) mval += w10 * mb[o10];
        if (vx0 && vy1) mval += w01 * mb[o01];
        if (vx1 && vy1) mval += w11 * mb[o11];
        size_t baseNP = ((size_t)n * NHD + h) * NP + p;
        outm[baseNP] = mval;
        smask[h][p] = mval;

        // x2d: border padding, 2 channels
        const float* xb0 = x2d + (size_t)img * 2 * HW;
        const float* xb1 = xb0 + HW;
        float xs0 = w00 * xb0[o00] + w10 * xb0[o10] + w01 * xb0[o01] + w11 * xb0[o11];
        float xs1 = w00 * xb1[o00] + w10 * xb1[o10] + w01 * xb1[o01] + w11 * xb1[o11];
        size_t xbase = (((size_t)n * NHD + h) * 2) * NP + p;
        outx[xbase]      = xs0;
        outx[xbase + NP] = xs1;
    }
    __syncwarp();

    // ---------- phase 2: lane = channel d ----------
    const int d = lane;
    const float qd = query[(size_t)n * EMBED + h * HD + d];
    const float* kb = g_ktr + (size_t)img * HW * EMBED + h * HD + d;
    const float* vb = g_vtr + (size_t)img * HW * EMBED + h * HD + d;

    float areg = 0.f;
#pragma unroll 4
    for (int p = 0; p < NP; p++) {
        int b0 = soff[h][0][p], b1 = soff[h][1][p];
        int b2 = soff[h][2][p], b3 = soff[h][3][p];
        float W0 = swt[h][0][p], W1 = swt[h][1][p];
        float W2 = swt[h][2][p], W3 = swt[h][3][p];
        float k0 = kb[b0], k1 = kb[b1], k2 = kb[b2], k3 = kb[b3];
        float v0 = vb[b0], v1 = vb[b1], v2 = vb[b2], v3 = vb[b3];
        float ks = W0 * k0 + W1 * k1 + W2 * k2 + W3 * k3;
        float vs = W0 * v0 + W1 * v1 + W2 * v2 + W3 * v3;
        vsm[h][d][p] = vs;
        float part = qd * ks;
#pragma unroll
        for (int o = 16; o; o >>= 1) part += __shfl_xor_sync(0xffffffffu, part, o);
        areg = (lane == p) ? part : areg;
    }
    areg *= 0.17677669529663687f;     // 1/sqrt(32)
    __syncwarp();

    // lane = point again for a / softmax
    size_t baseNP = ((size_t)n * NHD + h) * NP + lane;
    outa[baseNP] = areg;

    float mx = areg;
#pragma unroll
    for (int o = 16; o; o >>= 1) mx = fmaxf(mx, __shfl_xor_sync(0xffffffffu, mx, o));
    float e = expf(areg - mx);
    float ssum = e;
#pragma unroll
    for (int o = 16; o; o >>= 1) ssum += __shfl_xor_sync(0xffffffffu, ssum, o);
    float asv = e / ssum * smask[h][lane];
    asms[h][lane] = asv;
    __syncwarp();

    // v_samples out, coalesced (lane = p)
    float* outvb = outv + (((size_t)n * NHD + h) * HD) * NP + lane;
#pragma unroll
    for (int dd = 0; dd < HD; dd++)
        outvb[dd * NP] = vsm[h][dd][lane];

    // out[n,h,d] = sum_p asm[p] * v[d][p]   (lane = d)
    float o = 0.f;
#pragma unroll
    for (int pp = 0; pp < NP; pp++) o += asms[h][pp] * vsm[h][d][pp];
    attn[(size_t)n * EMBED + h * HD + d] = o;
}

// ============================================================================
// LayerNorm over 256 features; 1 block (256 thr) per row
// ============================================================================
__global__ __launch_bounds__(256) void ln_k(
    const float* __restrict__ x, const float* __restrict__ g,
    const float* __restrict__ b, float* __restrict__ y)
{
    __shared__ float red[8];
    const int r = blockIdx.x, t = threadIdx.x;
    float v = x[(size_t)r * EMBED + t];

    float s = v;
#pragma unroll
    for (int o = 16; o; o >>= 1) s += __shfl_xor_sync(0xffffffffu, s, o);
    if ((t & 31) == 0) red[t >> 5] = s;
    __syncthreads();
    float tot = 0.f;
#pragma unroll
    for (int i = 0; i < 8; i++) tot += red[i];
    float mean = tot * (1.f / 256.f);
    float d = v - mean;
    __syncthreads();

    s = d * d;
#pragma unroll
    for (int o = 16; o; o >>= 1) s += __shfl_xor_sync(0xffffffffu, s, o);
    if ((t & 31) == 0) red[t >> 5] = s;
    __syncthreads();
    tot = 0.f;
#pragma unroll
    for (int i = 0; i < 8; i++) tot += red[i];
    float inv = rsqrtf(tot * (1.f / 256.f) + 1e-5f);
    y[(size_t)r * EMBED + t] = d * inv * g[t] + b[t];
}

// ============================================================================
extern "C" void kernel_launch(void* const* d_in, const int* in_sizes, int n_in,
                              void* d_out, int out_size)
{
    const float* query   = (const float*)d_in[0];
    const float* obj_emb = (const float*)d_in[1];
    const float* key_f   = (const float*)d_in[2];
    const float* value   = (const float*)d_in[3];
    const float* x2d     = (const float*)d_in[4];
    const float* maskp   = (const float*)d_in[5];
    const float* xy      = (const float*)d_in[6];
    const float* strides = (const float*)d_in[7];
    const int*   imgind  = (const int*  )d_in[8];
    const float* w_off   = (const float*)d_in[9];
    const float* b_off   = (const float*)d_in[10];
    const float* w_out   = (const float*)d_in[11];
    const float* b_out   = (const float*)d_in[12];
    const float* ln1g    = (const float*)d_in[13];
    const float* ln1b    = (const float*)d_in[14];
    const float* w1      = (const float*)d_in[15];
    const float* b1      = (const float*)d_in[16];
    const float* w2      = (const float*)d_in[17];
    const float* b2      = (const float*)d_in[18];
    const float* ln2g    = (const float*)d_in[19];
    const float* ln2b    = (const float*)d_in[20];

    float* out  = (float*)d_out;
    float* outv = out  + (size_t)NOBJ * EMBED;
    float* outa = outv + (size_t)NOBJ * NHD * HD * NP;
    float* outm = outa + (size_t)NOBJ * NHD * NP;
    float* outx = outm + (size_t)NOBJ * NHD * NP;

    float *p_loc, *p_attn, *p_x1, *p_x1ln, *p_hid, *p_x2;
    cudaGetSymbolAddress((void**)&p_loc,  g_loc);
    cudaGetSymbolAddress((void**)&p_attn, g_attn);
    cudaGetSymbolAddress((void**)&p_x1,   g_x1);
    cudaGetSymbolAddress((void**)&p_x1ln, g_x1ln);
    cudaGetSymbolAddress((void**)&p_hid,  g_hid);
    cudaGetSymbolAddress((void**)&p_x2,   g_x2);

    // 0) transpose key/value -> (img, hw, embed)
    transpose_k<<<dim3(HW / 32, EMBED / 32, NUM_IMG * 2), 256>>>(key_f, value);

    // 1) offsets GEMM -> sample coords
    sgemm_k<0><<<dim3(512 / 64, NOBJ / 64), 128>>>(
        obj_emb, w_off, b_off, nullptr, p_loc, NOBJ, 512, EMBED, xy, strides);

    // 2) gather + attention + sample outputs
    sampler_k<<<NOBJ, 256>>>(query, x2d, maskp, imgind, p_loc,
                             outv, outa, outm, outx, p_attn);

    // 3) w_out GEMM + bias + residual(obj_emb)
    sgemm_k<1><<<dim3(EMBED / 64, NOBJ / 64), 128>>>(
        p_attn, w_out, b_out, obj_emb, p_x1, NOBJ, EMBED, EMBED, nullptr, nullptr);

    // 4) LN1
    ln_k<<<NOBJ, 256>>>(p_x1, ln1g, ln1b, p_x1ln);

    // 5) FFN up + relu
    sgemm_k<2><<<dim3(FFN_D / 64, NOBJ / 64), 128>>>(
        p_x1ln, w1, b1, nullptr, p_hid, NOBJ, FFN_D, EMBED, nullptr, nullptr);

    // 6) FFN down + bias + residual(x1ln)
    sgemm_k<3><<<dim3(EMBED / 64, NOBJ / 64), 128>>>(
        p_hid, w2, b2, p_x1ln, p_x2, NOBJ, EMBED, FFN_D, nullptr, nullptr);

    // 7) LN2 -> final out
    ln_k<<<NOBJ, 256>>>(p_x2, ln2g, ln2b, out);
}

// round 8
// speedup vs baseline: 1.0324x; 1.0324x over previous
#include <cuda_runtime.h>
#include <math.h>

#define NOBJ  2048
#define EMBED 256
#define NHD   8
#define NP    32
#define HD    32
#define FFN_D 1024
#define HIMG  160
#define WIMG  160
#define HW    (HIMG*WIMG)

// ---- scratch (device globals; no allocations allowed) ----
__device__ float g_loc [NOBJ*NHD*NP*2];
__device__ float g_attn[NOBJ*EMBED];
__device__ float g_x1  [NOBJ*EMBED];
__device__ float g_x1ln[NOBJ*EMBED];
__device__ float g_hid [NOBJ*FFN_D];
__device__ float g_x2  [NOBJ*EMBED];

// ============================================================================
// TF32 helpers
// ============================================================================
__device__ __forceinline__ unsigned f2tf32(float x) {
    unsigned u;
    asm("cvt.rna.tf32.f32 %0, %1;" : "=r"(u) : "f"(x));
    return u;
}
__device__ __forceinline__ void mma_tf32(float* d, const unsigned* a, const unsigned* b) {
    asm volatile(
        "mma.sync.aligned.m16n8k8.row.col.f32.tf32.tf32.f32 "
        "{%0,%1,%2,%3}, {%4,%5,%6,%7}, {%8,%9}, {%0,%1,%2,%3};"
        : "+f"(d[0]), "+f"(d[1]), "+f"(d[2]), "+f"(d[3])
        : "r"(a[0]), "r"(a[1]), "r"(a[2]), "r"(a[3]), "r"(b[0]), "r"(b[1]));
}

// ============================================================================
// TF32 tensor-core GEMM (3xTF32 for fp32-class accuracy).
// C(MxN) = A(MxK) @ B(KxN), row-major. Block tile 128x64, 256 thr (8 warps),
// warp tile 32x32 (2 m-frags x 4 n-frags), K-chunk 8, double-buffered smem.
// EPI 0: offsets -> sample coords   EPI 1/3: +bias +res   EPI 2: relu(+bias)
// ============================================================================
template<int EPI>
__global__ __launch_bounds__(256) void tgemm_k(
    const float* __restrict__ A, const float* __restrict__ B,
    const float* __restrict__ bias, const float* __restrict__ res,
    float* __restrict__ C, int M, int N, int K,
    const float* __restrict__ xy, const float* __restrict__ strd)
{
    __shared__ unsigned As_hi[2][8][136];
    __shared__ unsigned As_lo[2][8][136];
    __shared__ unsigned Bs_hi[2][8][72];
    __shared__ unsigned Bs_lo[2][8][72];

    const int tid  = threadIdx.x;
    const int lane = tid & 31;
    const int wid  = tid >> 5;
    const int m_warp = (wid & 3) * 32;   // 0,32,64,96
    const int n_warp = (wid >> 2) * 32;  // 0,32
    const int row0 = blockIdx.y * 128;
    const int col0 = blockIdx.x * 64;

    // loader indices
    const int am = tid >> 1;             // 0..127
    const int ak = (tid & 1) * 4;        // 0 or 4
    const int bk = tid >> 4;             // 0..15 (use <8)
    const int bn = (tid & 15) * 4;       // 0..60

    float acc[2][4][4];
#pragma unroll
    for (int mi = 0; mi < 2; mi++)
#pragma unroll
        for (int ni = 0; ni < 4; ni++)
#pragma unroll
            for (int r = 0; r < 4; r++) acc[mi][ni][r] = 0.f;

    const int nc = K >> 3;

    // prologue: global loads of chunk 0
    float4 aR = *(const float4*)(A + (size_t)(row0 + am) * K + ak);
    float4 bR = make_float4(0.f, 0.f, 0.f, 0.f);
    if (bk < 8) bR = *(const float4*)(B + (size_t)bk * N + col0 + bn);

    for (int c = 0; c < nc; c++) {
        const int buf = c & 1;
        // convert + store chunk c
        {
            float a4[4] = {aR.x, aR.y, aR.z, aR.w};
#pragma unroll
            for (int i = 0; i < 4; i++) {
                unsigned hi = f2tf32(a4[i]);
                float lo = a4[i] - __uint_as_float(hi);
                As_hi[buf][ak + i][am] = hi;
                As_lo[buf][ak + i][am] = f2tf32(lo);
            }
            if (bk < 8) {
                float b4[4] = {bR.x, bR.y, bR.z, bR.w};
#pragma unroll
                for (int i = 0; i < 4; i++) {
                    unsigned hi = f2tf32(b4[i]);
                    float lo = b4[i] - __uint_as_float(hi);
                    Bs_hi[buf][bk][bn + i] = hi;
                    Bs_lo[buf][bk][bn + i] = f2tf32(lo);
                }
            }
        }
        __syncthreads();

        // prefetch chunk c+1
        if (c + 1 < nc) {
            int kt = (c + 1) * 8;
            aR = *(const float4*)(A + (size_t)(row0 + am) * K + kt + ak);
            if (bk < 8) bR = *(const float4*)(B + (size_t)(kt + bk) * N + col0 + bn);
        }

        // compute chunk c
        {
            const int krow = lane & 3;
            const int mrow = m_warp + (lane >> 2);
            unsigned ah[2][4], al[2][4], bh[4][2], bl[4][2];
#pragma unroll
            for (int mi = 0; mi < 2; mi++) {
                int r = mrow + mi * 16;
                ah[mi][0] = As_hi[buf][krow    ][r];
                ah[mi][1] = As_hi[buf][krow    ][r + 8];
                ah[mi][2] = As_hi[buf][krow + 4][r];
                ah[mi][3] = As_hi[buf][krow + 4][r + 8];
                al[mi][0] = As_lo[buf][krow    ][r];
                al[mi][1] = As_lo[buf][krow    ][r + 8];
                al[mi][2] = As_lo[buf][krow + 4][r];
                al[mi][3] = As_lo[buf][krow + 4][r + 8];
            }
#pragma unroll
            for (int ni = 0; ni < 4; ni++) {
                int cc = n_warp + ni * 8 + (lane >> 2);
                bh[ni][0] = Bs_hi[buf][krow    ][cc];
                bh[ni][1] = Bs_hi[buf][krow + 4][cc];
                bl[ni][0] = Bs_lo[buf][krow    ][cc];
                bl[ni][1] = Bs_lo[buf][krow + 4][cc];
            }
#pragma unroll
            for (int mi = 0; mi < 2; mi++)
#pragma unroll
                for (int ni = 0; ni < 4; ni++) {
                    mma_tf32(acc[mi][ni], al[mi], bh[ni]);
                    mma_tf32(acc[mi][ni], ah[mi], bl[ni]);
                    mma_tf32(acc[mi][ni], ah[mi], bh[ni]);
                }
        }
        __syncthreads();
    }

    // ---- epilogue ----
#pragma unroll
    for (int mi = 0; mi < 2; mi++) {
#pragma unroll
        for (int rh = 0; rh < 2; rh++) {
            int r = row0 + m_warp + mi * 16 + (lane >> 2) + rh * 8;
            float st = 0.f, bx = 0.f, by = 0.f;
            if (EPI == 0) { st = strd[r]; bx = xy[2 * r]; by = xy[2 * r + 1]; }
#pragma unroll
            for (int ni = 0; ni < 4; ni++) {
                int cidx = col0 + n_warp + ni * 8 + 2 * (lane & 3);
                float v0 = acc[mi][ni][rh * 2 + 0] + bias[cidx];
                float v1 = acc[mi][ni][rh * 2 + 1] + bias[cidx + 1];
                size_t oidx = (size_t)r * N + cidx;
                if (EPI == 0) {
                    // cidx even -> x coord, cidx+1 -> y coord
                    float lx = bx + v0 * st;
                    float ly = by + v1 * st;
                    float gx = lx * (2.0f / 640.0f) - 1.0f;
                    float gy = ly * (2.0f / 640.0f) - 1.0f;
                    float2 o;
                    o.x = ((gx + 1.0f) * 160.0f - 1.0f) * 0.5f;
                    o.y = ((gy + 1.0f) * 160.0f - 1.0f) * 0.5f;
                    *(float2*)(C + oidx) = o;
                } else if (EPI == 1 || EPI == 3) {
                    float2 rr = *(const float2*)(res + oidx);
                    float2 o; o.x = v0 + rr.x; o.y = v1 + rr.y;
                    *(float2*)(C + oidx) = o;
                } else {
                    float2 o; o.x = fmaxf(v0, 0.f); o.y = fmaxf(v1, 0.f);
                    *(float2*)(C + oidx) = o;
                }
            }
        }
    }
}

// ============================================================================
// Sampler (planar layout, R5 version): 1 block/object, warp = head, lane = pt.
// ============================================================================
__global__ __launch_bounds__(256) void sampler_k(
    const float* __restrict__ query, const float* __restrict__ key,
    const float* __restrict__ val,   const float* __restrict__ x2d,
    const float* __restrict__ maskp, const int*   __restrict__ imgind,
    const float* __restrict__ loc,
    float* __restrict__ outv, float* __restrict__ outa,
    float* __restrict__ outm, float* __restrict__ outx,
    float* __restrict__ attn)
{
    __shared__ float qs  [NHD][HD];
    __shared__ float vsm [NHD][HD][NP + 1];
    __shared__ float asms[NHD][NP];

    const int n   = blockIdx.x;
    const int tid = threadIdx.x;
    const int h   = tid >> 5;
    const int p   = tid & 31;

    qs[h][p] = query[(size_t)n * EMBED + h * HD + p];
    const int img = imgind[n];

    float2 l2 = ((const float2*)loc)[((size_t)n * NHD + h) * NP + p];
    float ix = l2.x, iy = l2.y;
    float x0f = floorf(ix), y0f = floorf(iy);
    float wx1 = ix - x0f,   wy1 = iy - y0f;
    float wx0 = 1.f - wx1,  wy0 = 1.f - wy1;
    int x0 = (int)x0f, y0 = (int)y0f;
    int x1i = x0 + 1,  y1i = y0 + 1;
    int xc0 = min(max(x0, 0), WIMG - 1), xc1 = min(max(x1i, 0), WIMG - 1);
    int yc0 = min(max(y0, 0), HIMG - 1), yc1 = min(max(y1i, 0), HIMG - 1);
    float w00 = wx0 * wy0, w10 = wx1 * wy0, w01 = wx0 * wy1, w11 = wx1 * wy1;
    int o00 = yc0 * WIMG + xc0, o10 = yc0 * WIMG + xc1;
    int o01 = yc1 * WIMG + xc0, o11 = yc1 * WIMG + xc1;

    const float* kb = key + ((size_t)img * EMBED + h * HD) * HW;
    const float* vb = val + ((size_t)img * EMBED + h * HD) * HW;

    __syncwarp();

    float a = 0.f;
    float* outvb = outv + (((size_t)n * NHD + h) * HD) * NP + p;
#pragma unroll 4
    for (int d = 0; d < HD; d++) {
        const float* kp = kb + d * HW;
        float ks = w00 * kp[o00] + w10 * kp[o10] + w01 * kp[o01] + w11 * kp[o11];
        a += qs[h][d] * ks;
        const float* vp = vb + d * HW;
        float vs = w00 * vp[o00] + w10 * vp[o10] + w01 * vp[o01] + w11 * vp[o11];
        vsm[h][d][p] = vs;
        outvb[d * NP] = vs;
    }
    a *= 0.17677669529663687f;
    size_t baseNP = ((size_t)n * NHD + h) * NP + p;
    outa[baseNP] = a;

    bool vx0 = (x0  >= 0) && (x0  < WIMG), vx1 = (x1i >= 0) && (x1i < WIMG);
    bool vy0 = (y0  >= 0) && (y0  < HIMG), vy1 = (y1i >= 0) && (y1i < HIMG);
    const float* mb = maskp + (size_t)img * HW;
    float mval = 0.f;
    if (vx0 && vy0) mval += w00 * mb[o00];
    if (vx1 && vy0) mval += w10 * mb[o10];
    if (vx0 && vy1) mval += w01 * mb[o01];
    if (vx1 && vy1) mval += w11 * mb[o11];
    outm[baseNP] = mval;

    const float* xb0 = x2d + (size_t)img * 2 * HW;
    const float* xb1 = xb0 + HW;
    float xs0 = w00 * xb0[o00] + w10 * xb0[o10] + w01 * xb0[o01] + w11 * xb0[o11];
    float xs1 = w00 * xb1[o00] + w10 * xb1[o10] + w01 * xb1[o01] + w11 * xb1[o11];
    size_t xbase = (((size_t)n * NHD + h) * 2) * NP + p;
    outx[xbase]      = xs0;
    outx[xbase + NP] = xs1;

    float mx = a;
#pragma unroll
    for (int o = 16; o; o >>= 1) mx = fmaxf(mx, __shfl_xor_sync(0xffffffffu, mx, o));
    float e = expf(a - mx);
    float ssum = e;
#pragma unroll
    for (int o = 16; o; o >>= 1) ssum += __shfl_xor_sync(0xffffffffu, ssum, o);
    float asv = e / ssum * mval;
    asms[h][p] = asv;
    __syncwarp();

    const int d = p;
    float o = 0.f;
#pragma unroll
    for (int pp = 0; pp < NP; pp++) o += asms[h][pp] * vsm[h][d][pp];
    attn[(size_t)n * EMBED + h * HD + d] = o;
}

// ============================================================================
// LayerNorm over 256 features; 1 block (256 thr) per row
// ============================================================================
__global__ __launch_bounds__(256) void ln_k(
    const float* __restrict__ x, const float* __restrict__ g,
    const float* __restrict__ b, float* __restrict__ y)
{
    __shared__ float red[8];
    const int r = blockIdx.x, t = threadIdx.x;
    float v = x[(size_t)r * EMBED + t];

    float s = v;
#pragma unroll
    for (int o = 16; o; o >>= 1) s += __shfl_xor_sync(0xffffffffu, s, o);
    if ((t & 31) == 0) red[t >> 5] = s;
    __syncthreads();
    float tot = 0.f;
#pragma unroll
    for (int i = 0; i < 8; i++) tot += red[i];
    float mean = tot * (1.f / 256.f);
    float d = v - mean;
    __syncthreads();

    s = d * d;
#pragma unroll
    for (int o = 16; o; o >>= 1) s += __shfl_xor_sync(0xffffffffu, s, o);
    if ((t & 31) == 0) red[t >> 5] = s;
    __syncthreads();
    tot = 0.f;
#pragma unroll
    for (int i = 0; i < 8; i++) tot += red[i];
    float inv = rsqrtf(tot * (1.f / 256.f) + 1e-5f);
    y[(size_t)r * EMBED + t] = d * inv * g[t] + b[t];
}

// ============================================================================
extern "C" void kernel_launch(void* const* d_in, const int* in_sizes, int n_in,
                              void* d_out, int out_size)
{
    const float* query   = (const float*)d_in[0];
    const float* obj_emb = (const float*)d_in[1];
    const float* key_f   = (const float*)d_in[2];
    const float* value   = (const float*)d_in[3];
    const float* x2d     = (const float*)d_in[4];
    const float* maskp   = (const float*)d_in[5];
    const float* xy      = (const float*)d_in[6];
    const float* strides = (const float*)d_in[7];
    const int*   imgind  = (const int*  )d_in[8];
    const float* w_off   = (const float*)d_in[9];
    const float* b_off   = (const float*)d_in[10];
    const float* w_out   = (const float*)d_in[11];
    const float* b_out   = (const float*)d_in[12];
    const float* ln1g    = (const float*)d_in[13];
    const float* ln1b    = (const float*)d_in[14];
    const float* w1      = (const float*)d_in[15];
    const float* b1      = (const float*)d_in[16];
    const float* w2      = (const float*)d_in[17];
    const float* b2      = (const float*)d_in[18];
    const float* ln2g    = (const float*)d_in[19];
    const float* ln2b    = (const float*)d_in[20];

    float* out  = (float*)d_out;
    float* outv = out  + (size_t)NOBJ * EMBED;
    float* outa = outv + (size_t)NOBJ * NHD * HD * NP;
    float* outm = outa + (size_t)NOBJ * NHD * NP;
    float* outx = outm + (size_t)NOBJ * NHD * NP;

    float *p_loc, *p_attn, *p_x1, *p_x1ln, *p_hid, *p_x2;
    cudaGetSymbolAddress((void**)&p_loc,  g_loc);
    cudaGetSymbolAddress((void**)&p_attn, g_attn);
    cudaGetSymbolAddress((void**)&p_x1,   g_x1);
    cudaGetSymbolAddress((void**)&p_x1ln, g_x1ln);
    cudaGetSymbolAddress((void**)&p_hid,  g_hid);
    cudaGetSymbolAddress((void**)&p_x2,   g_x2);

    // 1) offsets GEMM -> sample coords   (M=2048, N=512, K=256)
    tgemm_k<0><<<dim3(512 / 64, NOBJ / 128), 256>>>(
        obj_emb, w_off, b_off, nullptr, p_loc, NOBJ, 512, EMBED, xy, strides);

    // 2) gather + attention + sample outputs
    sampler_k<<<NOBJ, 256>>>(query, key_f, value, x2d, maskp, imgind, p_loc,
                             outv, outa, outm, outx, p_attn);

    // 3) w_out GEMM + bias + residual(obj_emb)
    tgemm_k<1><<<dim3(EMBED / 64, NOBJ / 128), 256>>>(
        p_attn, w_out, b_out, obj_emb, p_x1, NOBJ, EMBED, EMBED, nullptr, nullptr);

    // 4) LN1
    ln_k<<<NOBJ, 256>>>(p_x1, ln1g, ln1b, p_x1ln);

    // 5) FFN up + relu
    tgemm_k<2><<<dim3(FFN_D / 64, NOBJ / 128), 256>>>(
        p_x1ln, w1, b1, nullptr, p_hid, NOBJ, FFN_D, EMBED, nullptr, nullptr);

    // 6) FFN down + bias + residual(x1ln)
    tgemm_k<3><<<dim3(EMBED / 64, NOBJ / 128), 256>>>(
        p_hid, w2, b2, p_x1ln, p_x2, NOBJ, EMBED, FFN_D, nullptr, nullptr);

    // 7) LN2 -> final out
    ln_k<<<NOBJ, 256>>>(p_x2, ln2g, ln2b, out);
}

// round 10
// speedup vs baseline: 1.1533x; 1.1171x over previous
#include <cuda_runtime.h>
#include <math.h>
#include <stdint.h>

#define NOBJ  2048
#define EMBED 256
#define NHD   8
#define NP    32
#define HD    32
#define FFN_D 1024
#define HIMG  160
#define WIMG  160
#define HW    (HIMG*WIMG)

// ---- scratch (device globals; no allocations allowed) ----
__device__ float g_loc  [NOBJ*NHD*NP*2];
__device__ float g_attn [NOBJ*EMBED];
__device__ float g_x1ln [NOBJ*EMBED];
__device__ float g_hid  [NOBJ*FFN_D];
__device__ float g_part [2*NOBJ*EMBED];   // split-K partial sums

// ============================================================================
// f32x2 helpers (packed dual-lane fp32 FMA — sm_100-family base feature)
// ============================================================================
__device__ __forceinline__ unsigned long long pack2(float x) {
    unsigned long long r;
    asm("mov.b64 %0, {%1, %1};" : "=l"(r) : "r"(__float_as_uint(x)));
    return r;
}
__device__ __forceinline__ void ffma2(unsigned long long& d,
                                      unsigned long long a, unsigned long long b) {
    asm("fma.rn.f32x2 %0, %1, %2, %0;" : "+l"(d) : "l"(a), "l"(b));
}
__device__ __forceinline__ float2 unpack2(unsigned long long v) {
    unsigned lo, hi;
    asm("mov.b64 {%0, %1}, %2;" : "=r"(lo), "=r"(hi) : "l"(v));
    return make_float2(__uint_as_float(lo), __uint_as_float(hi));
}

// ============================================================================
// FFMA2 GEMM: C(MxN) = A(M x kLen slice) @ B(KxN), row-major.
// Block tile 128x64, 256 threads (8 warps), per-thread 4m x 8n (4x4 f32x2).
// k-chunk 16, double-buffered smem. blockIdx.z selects K slice (split-K).
// EPI 0: bias -> sample coords    EPI 2: relu(+bias)    EPI 4: raw partial
// ============================================================================
template<int EPI>
__global__ __launch_bounds__(256) void fgemm(
    const float* __restrict__ A, const float* __restrict__ B,
    const float* __restrict__ bias, float* __restrict__ C,
    int M, int N, int K, int kLen,
    const float* __restrict__ xy, const float* __restrict__ strd)
{
    __shared__ __align__(16) float As[2][16][132];   // [buf][k][m]
    __shared__ __align__(16) float Bs[2][16][68];    // [buf][k][n]

    const int tid  = threadIdx.x;
    const int tx   = tid & 7;        // n-group: cols tx*8 .. tx*8+7
    const int ty   = tid >> 3;       // m-group: rows ty*4 .. ty*4+3
    const int row0 = blockIdx.y * 128;
    const int col0 = blockIdx.x * 64;
    const int kBase = blockIdx.z * kLen;

    unsigned long long acc[4][4];
#pragma unroll
    for (int i = 0; i < 4; i++)
#pragma unroll
        for (int j = 0; j < 4; j++) acc[i][j] = 0ull;

    // loader indices
    const int am0 = tid >> 2;               // 0..63   (A: 2 float4 per thread)
    const int ak  = (tid & 3) << 2;         // 0,4,8,12
    const int bk  = tid >> 4;               // 0..15   (B: 1 float4 per thread)
    const int bn  = (tid & 15) << 2;        // 0..60

    const int S = kLen >> 4;

    // prologue: prefetch chunk 0
    float4 aR0 = *(const float4*)(A + (size_t)(row0 + am0)      * K + kBase + ak);
    float4 aR1 = *(const float4*)(A + (size_t)(row0 + am0 + 64) * K + kBase + ak);
    float4 bR  = *(const float4*)(B + (size_t)(kBase + bk) * N + col0 + bn);

    for (int c = 0; c < S; c++) {
        const int b = c & 1;
        // store chunk c (A transposed to [k][m])
        As[b][ak + 0][am0]      = aR0.x;
        As[b][ak + 1][am0]      = aR0.y;
        As[b][ak + 2][am0]      = aR0.z;
        As[b][ak + 3][am0]      = aR0.w;
        As[b][ak + 0][am0 + 64] = aR1.x;
        As[b][ak + 1][am0 + 64] = aR1.y;
        As[b][ak + 2][am0 + 64] = aR1.z;
        As[b][ak + 3][am0 + 64] = aR1.w;
        *(float4*)&Bs[b][bk][bn] = bR;
        __syncthreads();

        // prefetch chunk c+1
        if (c + 1 < S) {
            int k0 = kBase + (c + 1) * 16;
            aR0 = *(const float4*)(A + (size_t)(row0 + am0)      * K + k0 + ak);
            aR1 = *(const float4*)(A + (size_t)(row0 + am0 + 64) * K + k0 + ak);
            bR  = *(const float4*)(B + (size_t)(k0 + bk) * N + col0 + bn);
        }

        // compute chunk c
#pragma unroll
        for (int k = 0; k < 16; k++) {
            float4 a4 = *(const float4*)&As[b][k][ty * 4];
            unsigned long long ap0 = pack2(a4.x);
            unsigned long long ap1 = pack2(a4.y);
            unsigned long long ap2 = pack2(a4.z);
            unsigned long long ap3 = pack2(a4.w);
            unsigned long long b0 = *(const unsigned long long*)&Bs[b][k][tx * 8 + 0];
            unsigned long long b1 = *(const unsigned long long*)&Bs[b][k][tx * 8 + 2];
            unsigned long long b2 = *(const unsigned long long*)&Bs[b][k][tx * 8 + 4];
            unsigned long long b3 = *(const unsigned long long*)&Bs[b][k][tx * 8 + 6];
            ffma2(acc[0][0], ap0, b0); ffma2(acc[0][1], ap0, b1);
            ffma2(acc[0][2], ap0, b2); ffma2(acc[0][3], ap0, b3);
            ffma2(acc[1][0], ap1, b0); ffma2(acc[1][1], ap1, b1);
            ffma2(acc[1][2], ap1, b2); ffma2(acc[1][3], ap1, b3);
            ffma2(acc[2][0], ap2, b0); ffma2(acc[2][1], ap2, b1);
            ffma2(acc[2][2], ap2, b2); ffma2(acc[2][3], ap2, b3);
            ffma2(acc[3][0], ap3, b0); ffma2(acc[3][1], ap3, b1);
            ffma2(acc[3][2], ap3, b2); ffma2(acc[3][3], ap3, b3);
        }
        __syncthreads();
    }

    // ---- epilogue ----
#pragma unroll
    for (int mi = 0; mi < 4; mi++) {
        const int r = row0 + ty * 4 + mi;
        float st = 0.f, bx = 0.f, by = 0.f;
        if (EPI == 0) { st = strd[r]; bx = xy[2 * r]; by = xy[2 * r + 1]; }
#pragma unroll
        for (int nj = 0; nj < 4; nj++) {
            const int cidx = col0 + tx * 8 + 2 * nj;
            float2 v = unpack2(acc[mi][nj]);
            size_t oidx = (size_t)r * N + cidx;
            float2 o;
            if (EPI == 0) {
                float v0 = v.x + bias[cidx];
                float v1 = v.y + bias[cidx + 1];
                float lx = bx + v0 * st;           // even col = x
                float ly = by + v1 * st;           // odd  col = y
                float gx = lx * (2.0f / 640.0f) - 1.0f;
                float gy = ly * (2.0f / 640.0f) - 1.0f;
                o.x = ((gx + 1.0f) * 160.0f - 1.0f) * 0.5f;
                o.y = ((gy + 1.0f) * 160.0f - 1.0f) * 0.5f;
            } else if (EPI == 2) {
                o.x = fmaxf(v.x + bias[cidx],     0.f);
                o.y = fmaxf(v.y + bias[cidx + 1], 0.f);
            } else {                               // EPI 4: raw partial
                o.x = v.x; o.y = v.y;
                oidx += (size_t)blockIdx.z * M * N;
            }
            *(float2*)(C + oidx) = o;
        }
    }
}

// ============================================================================
// Combine split-K partials + bias + residual, then LayerNorm. 1 block / row.
// ============================================================================
__global__ __launch_bounds__(256) void comb_ln_k(
    const float* __restrict__ part, const float* __restrict__ bias,
    const float* __restrict__ res,  const float* __restrict__ g,
    const float* __restrict__ b,    float* __restrict__ y)
{
    __shared__ float red[8];
    const int r = blockIdx.x, t = threadIdx.x;
    const size_t idx = (size_t)r * EMBED + t;
    float v = part[idx] + part[(size_t)NOBJ * EMBED + idx] + bias[t] + res[idx];

    float s = v;
#pragma unroll
    for (int o = 16; o; o >>= 1) s += __shfl_xor_sync(0xffffffffu, s, o);
    if ((t & 31) == 0) red[t >> 5] = s;
    __syncthreads();
    float tot = 0.f;
#pragma unroll
    for (int i = 0; i < 8; i++) tot += red[i];
    float mean = tot * (1.f / 256.f);
    float d = v - mean;
    __syncthreads();

    s = d * d;
#pragma unroll
    for (int o = 16; o; o >>= 1) s += __shfl_xor_sync(0xffffffffu, s, o);
    if ((t & 31) == 0) red[t >> 5] = s;
    __syncthreads();
    tot = 0.f;
#pragma unroll
    for (int i = 0; i < 8; i++) tot += red[i];
    float inv = rsqrtf(tot * (1.f / 256.f) + 1e-5f);
    y[idx] = d * inv * g[t] + b[t];
}

// ============================================================================
// Sampler (planar, known-good): 1 block/object, warp = head, lane = point
// ============================================================================
__global__ __launch_bounds__(256) void sampler_k(
    const float* __restrict__ query, const float* __restrict__ key,
    const float* __restrict__ val,   const float* __restrict__ x2d,
    const float* __restrict__ maskp, const int*   __restrict__ imgind,
    const float* __restrict__ loc,
    float* __restrict__ outv, float* __restrict__ outa,
    float* __restrict__ outm, float* __restrict__ outx,
    float* __restrict__ attn)
{
    __shared__ float qs  [NHD][HD];
    __shared__ float vsm [NHD][HD][NP + 1];
    __shared__ float asms[NHD][NP];

    const int n   = blockIdx.x;
    const int tid = threadIdx.x;
    const int h   = tid >> 5;
    const int p   = tid & 31;

    qs[h][p] = query[(size_t)n * EMBED + h * HD + p];
    const int img = imgind[n];

    float2 l2 = ((const float2*)loc)[((size_t)n * NHD + h) * NP + p];
    float ix = l2.x, iy = l2.y;
    float x0f = floorf(ix), y0f = floorf(iy);
    float wx1 = ix - x0f,   wy1 = iy - y0f;
    float wx0 = 1.f - wx1,  wy0 = 1.f - wy1;
    int x0 = (int)x0f, y0 = (int)y0f;
    int x1i = x0 + 1,  y1i = y0 + 1;
    int xc0 = min(max(x0, 0), WIMG - 1), xc1 = min(max(x1i, 0), WIMG - 1);
    int yc0 = min(max(y0, 0), HIMG - 1), yc1 = min(max(y1i, 0), HIMG - 1);
    float w00 = wx0 * wy0, w10 = wx1 * wy0, w01 = wx0 * wy1, w11 = wx1 * wy1;
    int o00 = yc0 * WIMG + xc0, o10 = yc0 * WIMG + xc1;
    int o01 = yc1 * WIMG + xc0, o11 = yc1 * WIMG + xc1;

    const float* kb = key + ((size_t)img * EMBED + h * HD) * HW;
    const float* vb = val + ((size_t)img * EMBED + h * HD) * HW;

    __syncwarp();

    float a = 0.f;
    float* outvb = outv + (((size_t)n * NHD + h) * HD) * NP + p;
#pragma unroll 4
    for (int d = 0; d < HD; d++) {
        const float* kp = kb + d * HW;
        float ks = w00 * kp[o00] + w10 * kp[o10] + w01 * kp[o01] + w11 * kp[o11];
        a += qs[h][d] * ks;
        const float* vp = vb + d * HW;
        float vs = w00 * vp[o00] + w10 * vp[o10] + w01 * vp[o01] + w11 * vp[o11];
        vsm[h][d][p] = vs;
        outvb[d * NP] = vs;
    }
    a *= 0.17677669529663687f;
    size_t baseNP = ((size_t)n * NHD + h) * NP + p;
    outa[baseNP] = a;

    bool vx0 = (x0  >= 0) && (x0  < WIMG), vx1 = (x1i >= 0) && (x1i < WIMG);
    bool vy0 = (y0  >= 0) && (y0  < HIMG), vy1 = (y1i >= 0) && (y1i < HIMG);
    const float* mb = maskp + (size_t)img * HW;
    float mval = 0.f;
    if (vx0 && vy0) mval += w00 * mb[o00];
    if (vx1 && vy0) mval += w10 * mb[o10];
    if (vx0 && vy1) mval += w01 * mb[o01];
    if (vx1 && vy1) mval += w11 * mb[o11];
    outm[baseNP] = mval;

    const float* xb0 = x2d + (size_t)img * 2 * HW;
    const float* xb1 = xb0 + HW;
    float xs0 = w00 * xb0[o00] + w10 * xb0[o10] + w01 * xb0[o01] + w11 * xb0[o11];
    float xs1 = w00 * xb1[o00] + w10 * xb1[o10] + w01 * xb1[o01] + w11 * xb1[o11];
    size_t xbase = (((size_t)n * NHD + h) * 2) * NP + p;
    outx[xbase]      = xs0;
    outx[xbase + NP] = xs1;

    float mx = a;
#pragma unroll
    for (int o = 16; o; o >>= 1) mx = fmaxf(mx, __shfl_xor_sync(0xffffffffu, mx, o));
    float e = expf(a - mx);
    float ssum = e;
#pragma unroll
    for (int o = 16; o; o >>= 1) ssum += __shfl_xor_sync(0xffffffffu, ssum, o);
    float asv = e / ssum * mval;
    asms[h][p] = asv;
    __syncwarp();

    const int d = p;
    float o = 0.f;
#pragma unroll
    for (int pp = 0; pp < NP; pp++) o += asms[h][pp] * vsm[h][d][pp];
    attn[(size_t)n * EMBED + h * HD + d] = o;
}

// ============================================================================
extern "C" void kernel_launch(void* const* d_in, const int* in_sizes, int n_in,
                              void* d_out, int out_size)
{
    const float* query   = (const float*)d_in[0];
    const float* obj_emb = (const float*)d_in[1];
    const float* key_f   = (const float*)d_in[2];
    const float* value   = (const float*)d_in[3];
    const float* x2d     = (const float*)d_in[4];
    const float* maskp   = (const float*)d_in[5];
    const float* xy      = (const float*)d_in[6];
    const float* strides = (const float*)d_in[7];
    const int*   imgind  = (const int*  )d_in[8];
    const float* w_off   = (const float*)d_in[9];
    const float* b_off   = (const float*)d_in[10];
    const float* w_out   = (const float*)d_in[11];
    const float* b_out   = (const float*)d_in[12];
    const float* ln1g    = (const float*)d_in[13];
    const float* ln1b    = (const float*)d_in[14];
    const float* w1      = (const float*)d_in[15];
    const float* b1      = (const float*)d_in[16];
    const float* w2      = (const float*)d_in[17];
    const float* b2      = (const float*)d_in[18];
    const float* ln2g    = (const float*)d_in[19];
    const float* ln2b    = (const float*)d_in[20];

    float* out  = (float*)d_out;
    float* outv = out  + (size_t)NOBJ * EMBED;
    float* outa = outv + (size_t)NOBJ * NHD * HD * NP;
    float* outm = outa + (size_t)NOBJ * NHD * NP;
    float* outx = outm + (size_t)NOBJ * NHD * NP;

    float *p_loc, *p_attn, *p_x1ln, *p_hid, *p_part;
    cudaGetSymbolAddress((void**)&p_loc,  g_loc);
    cudaGetSymbolAddress((void**)&p_attn, g_attn);
    cudaGetSymbolAddress((void**)&p_x1ln, g_x1ln);
    cudaGetSymbolAddress((void**)&p_hid,  g_hid);
    cudaGetSymbolAddress((void**)&p_part, g_part);

    // 1) offsets GEMM -> sample coords  (M=2048, N=512, K=256)
    fgemm<0><<<dim3(512 / 64, NOBJ / 128, 1), 256>>>(
        obj_emb, w_off, b_off, p_loc, NOBJ, 512, EMBED, EMBED, xy, strides);

    // 2) gather + attention + sample outputs
    sampler_k<<<NOBJ, 256>>>(query, key_f, value, x2d, maskp, imgind, p_loc,
                             outv, outa, outm, outx, p_attn);

    // 3) w_out GEMM, split-K=2 -> partials
    fgemm<4><<<dim3(EMBED / 64, NOBJ / 128, 2), 256>>>(
        p_attn, w_out, nullptr, p_part, NOBJ, EMBED, EMBED, EMBED / 2,
        nullptr, nullptr);

    // 4) combine + bias + residual(obj_emb) + LN1 -> x1ln
    comb_ln_k<<<NOBJ, 256>>>(p_part, b_out, obj_emb, ln1g, ln1b, p_x1ln);

    // 5) FFN up + relu  (M=2048, N=1024, K=256)
    fgemm<2><<<dim3(FFN_D / 64, NOBJ / 128, 1), 256>>>(
        p_x1ln, w1, b1, p_hid, NOBJ, FFN_D, EMBED, EMBED, nullptr, nullptr);

    // 6) FFN down GEMM, split-K=2 -> partials  (K=1024)
    fgemm<4><<<dim3(EMBED / 64, NOBJ / 128, 2), 256>>>(
        p_hid, w2, nullptr, p_part, NOBJ, EMBED, FFN_D, FFN_D / 2,
        nullptr, nullptr);

    // 7) combine + bias + residual(x1ln) + LN2 -> final out
    comb_ln_k<<<NOBJ, 256>>>(p_part, b2, p_x1ln, ln2g, ln2b, out);
}